// round 3
// baseline (speedup 1.0000x reference)
#include <cuda_runtime.h>
#include <cstdint>

// Problem constants
#define NWIN 2048
#define NTOK 49
#define CDIM 192
#define NH   6
#define HD   32
#define NWMASK 64
#define NREL 169
#define QSCALE 0.17677669529663687f  // 1/sqrt(32)

// SMEM layout (floats)
#define XS_STRIDE 196   // 192 + 4 pad (bank-conflict mitigation, float4 aligned)
#define WS_STRIDE 196
#define KV_STRIDE 36    // 32 + 4 pad

#define XS_OFF 0
#define XS_FLOATS (NTOK * XS_STRIDE)                 // 9604
#define WS_OFF (XS_OFF + XS_FLOATS)
#define WS_FLOATS (64 * WS_STRIDE)                   // 12544
#define QS_OFF (WS_OFF + WS_FLOATS)
#define HKV_FLOATS (NH * NTOK * KV_STRIDE)           // 10584
#define KS_OFF (QS_OFF + HKV_FLOATS)
#define VS_OFF (KS_OFF + HKV_FLOATS)
#define BT_OFF (VS_OFF + HKV_FLOATS)                 // bias_table staged [169][6]
#define BT_FLOATS (NREL * NH)                        // 1014
#define RI_OFF (BT_OFF + BT_FLOATS)                  // rel_index staged as int
#define RI_WORDS (NTOK * NTOK)                       // 2401
#define SMEM_FLOATS (RI_OFF + RI_WORDS)              // 57199 -> 228796 B (< 232448 opt-in)

typedef unsigned long long ull;

__device__ __forceinline__ ull pack2(float lo, float hi) {
    ull r;
    asm("mov.b64 %0, {%1, %2};" : "=l"(r) : "f"(lo), "f"(hi));
    return r;
}
__device__ __forceinline__ void unpack2(ull v, float& lo, float& hi) {
    asm("mov.b64 {%0, %1}, %2;" : "=f"(lo), "=f"(hi) : "l"(v));
}
// packed fp32 FMA (Blackwell): d = a*b + d elementwise on 2 lanes
__device__ __forceinline__ void fma2(ull& d, ull a, ull b) {
#if defined(__CUDA_ARCH__) && (__CUDA_ARCH__ >= 1000)
    asm("fma.rn.f32x2 %0, %1, %2, %3;" : "=l"(d) : "l"(a), "l"(b), "l"(d));
#else
    float dl, dh, al, ah, bl, bh;
    unpack2(d, dl, dh); unpack2(a, al, ah); unpack2(b, bl, bh);
    dl = fmaf(al, bl, dl); dh = fmaf(ah, bh, dh);
    d = pack2(dl, dh);
#endif
}

__device__ __forceinline__ float f4get(const float4& v, int k) {
    return (k == 0) ? v.x : (k == 1) ? v.y : (k == 2) ? v.z : v.w;
}

// 64-row x 64-col register-tiled GEMM over K=192 from smem (rows 49..63 are
// garbage and discarded by callers). Each thread: 4 rows (ty+16i) x 4 cols
// (tx+16j), cols packed in pairs for fma.rn.f32x2.
__device__ __forceinline__ void gemm_tile(const float* __restrict__ src,
                                          const float* __restrict__ ws,
                                          int tx, int ty, ull acc[4][2]) {
#pragma unroll
    for (int i = 0; i < 4; i++) { acc[i][0] = 0ull; acc[i][1] = 0ull; }
#pragma unroll 4
    for (int k4 = 0; k4 < CDIM / 4; ++k4) {
        float4 xv[4], wv[4];
#pragma unroll
        for (int i = 0; i < 4; i++)
            xv[i] = ((const float4*)(src + (ty + 16 * i) * XS_STRIDE))[k4];
#pragma unroll
        for (int j = 0; j < 4; j++)
            wv[j] = ((const float4*)(ws + (tx + 16 * j) * WS_STRIDE))[k4];
#pragma unroll
        for (int kk = 0; kk < 4; kk++) {
            ull b0 = pack2(f4get(wv[0], kk), f4get(wv[1], kk));
            ull b1 = pack2(f4get(wv[2], kk), f4get(wv[3], kk));
#pragma unroll
            for (int i = 0; i < 4; i++) {
                float xf = f4get(xv[i], kk);
                ull a = pack2(xf, xf);
                fma2(acc[i][0], a, b0);
                fma2(acc[i][1], a, b1);
            }
        }
    }
}

__global__ __launch_bounds__(256, 1)
void win_msa_kernel(const float* __restrict__ x, const float* __restrict__ mask,
                    const float* __restrict__ qkv_w, const float* __restrict__ qkv_b,
                    const float* __restrict__ proj_w, const float* __restrict__ proj_b,
                    const float* __restrict__ bias_table,
                    const int* __restrict__ rel_index,
                    float* __restrict__ out)
{
    extern __shared__ float smf[];
    float* xs = smf + XS_OFF;   // x tile, later attention output (o)
    float* ws = smf + WS_OFF;   // weight tile (64 cols x 192 k)
    float* qs = smf + QS_OFF;   // [h][n][36]
    float* ks = smf + KS_OFF;
    float* vs = smf + VS_OFF;
    float* bts = smf + BT_OFF;  // bias_table [169][6]
    int*   ris = (int*)(smf + RI_OFF);  // rel_index [49*49]

    const int bw = blockIdx.x;
    const int tid = threadIdx.x;
    const int tx = tid & 15;
    const int ty = tid >> 4;

    // ---- load x window into smem; stage bias_table + rel_index ----
    {
        const float4* gx = (const float4*)(x + (size_t)bw * NTOK * CDIM);
        for (int it = tid; it < NTOK * (CDIM / 4); it += 256) {
            int r = it / (CDIM / 4), k4 = it % (CDIM / 4);
            ((float4*)(xs + r * XS_STRIDE))[k4] = gx[it];
        }
        for (int it = tid; it < NREL * NH; it += 256)
            bts[it] = bias_table[it];
        for (int it = tid; it < NTOK * NTOK; it += 256)
            ris[it] = rel_index[it];
    }
    __syncthreads();

    // ---- Phase 1: QKV projection, 9 column tiles of 64 ----
    for (int ct = 0; ct < 9; ++ct) {
        const float4* gw = (const float4*)qkv_w + (size_t)ct * 64 * (CDIM / 4);
        for (int it = tid; it < 64 * (CDIM / 4); it += 256) {
            int c = it / (CDIM / 4), k4 = it % (CDIM / 4);
            ((float4*)(ws + c * WS_STRIDE))[k4] = gw[it];
        }
        __syncthreads();

        ull acc[4][2];
        gemm_tile(xs, ws, tx, ty, acc);

        const int s = ct / 3;  // 0=q,1=k,2=v (constant per tile)
        float* dst = (s == 0) ? qs : (s == 1) ? ks : vs;
#pragma unroll
        for (int i = 0; i < 4; i++) {
            int r = ty + 16 * i;
            if (r < NTOK) {
                float y[4];
                unpack2(acc[i][0], y[0], y[1]);
                unpack2(acc[i][1], y[2], y[3]);
#pragma unroll
                for (int j = 0; j < 4; j++) {
                    int cg = ct * 64 + tx + 16 * j;
                    float val = y[j] + qkv_b[cg];
                    int rem = cg - s * CDIM;
                    int h = rem >> 5, d = rem & 31;
                    if (s == 0) val *= QSCALE;
                    dst[(h * NTOK + r) * KV_STRIDE + d] = val;
                }
            }
        }
        __syncthreads();
    }

    // ---- Phase 2: attention, one (head, query-row) per thread ----
    for (int t = tid; t < NH * NTOK; t += 256) {
        const int h = t / NTOK;
        const int qi = t - h * NTOK;

        float4 qv[8];
        const float4* qrow = (const float4*)(qs + (h * NTOK + qi) * KV_STRIDE);
#pragma unroll
        for (int d4 = 0; d4 < 8; ++d4) qv[d4] = qrow[d4];

        const float* mrow = mask + ((size_t)(bw & (NWMASK - 1)) * NTOK + qi) * NTOK;
        const int* ridx = ris + qi * NTOK;

        float p[NTOK];
        float mx = -1e30f;
#pragma unroll 1
        for (int j = 0; j < NTOK; ++j) {
            const float4* krow = (const float4*)(ks + (h * NTOK + j) * KV_STRIDE);
            float s = 0.f;
#pragma unroll
            for (int d4 = 0; d4 < 8; ++d4) {
                float4 kv = krow[d4];
                s += qv[d4].x * kv.x + qv[d4].y * kv.y + qv[d4].z * kv.z + qv[d4].w * kv.w;
            }
            s += bts[ridx[j] * NH + h] + mrow[j];
            p[j] = s;
            mx = fmaxf(mx, s);
        }
        float sum = 0.f;
#pragma unroll 1
        for (int j = 0; j < NTOK; ++j) {
            float e = __expf(p[j] - mx);
            p[j] = e;
            sum += e;
        }
        const float rinv = 1.0f / sum;

        float4 o[8];
#pragma unroll
        for (int d4 = 0; d4 < 8; ++d4) o[d4] = make_float4(0.f, 0.f, 0.f, 0.f);
#pragma unroll 1
        for (int j = 0; j < NTOK; ++j) {
            float pj = p[j];
            const float4* vrow = (const float4*)(vs + (h * NTOK + j) * KV_STRIDE);
#pragma unroll
            for (int d4 = 0; d4 < 8; ++d4) {
                float4 vv = vrow[d4];
                o[d4].x += pj * vv.x; o[d4].y += pj * vv.y;
                o[d4].z += pj * vv.z; o[d4].w += pj * vv.w;
            }
        }
        // write o into xs region (x no longer needed): os[qi][h*32+d]
        float4* orow = (float4*)(xs + qi * XS_STRIDE + h * HD);
#pragma unroll
        for (int d4 = 0; d4 < 8; ++d4)
            orow[d4] = make_float4(o[d4].x * rinv, o[d4].y * rinv,
                                   o[d4].z * rinv, o[d4].w * rinv);
    }
    __syncthreads();

    // ---- Phase 3: output projection, 3 column tiles of 64 ----
    for (int ct = 0; ct < 3; ++ct) {
        const float4* gw = (const float4*)proj_w + (size_t)ct * 64 * (CDIM / 4);
        for (int it = tid; it < 64 * (CDIM / 4); it += 256) {
            int c = it / (CDIM / 4), k4 = it % (CDIM / 4);
            ((float4*)(ws + c * WS_STRIDE))[k4] = gw[it];
        }
        __syncthreads();

        ull acc[4][2];
        gemm_tile(xs, ws, tx, ty, acc);

#pragma unroll
        for (int i = 0; i < 4; i++) {
            int r = ty + 16 * i;
            if (r < NTOK) {
                float y[4];
                unpack2(acc[i][0], y[0], y[1]);
                unpack2(acc[i][1], y[2], y[3]);
#pragma unroll
                for (int j = 0; j < 4; j++) {
                    int cg = ct * 64 + tx + 16 * j;
                    out[((size_t)bw * NTOK + r) * CDIM + cg] = y[j] + proj_b[cg];
                }
            }
        }
        __syncthreads();
    }
}

extern "C" void kernel_launch(void* const* d_in, const int* in_sizes, int n_in,
                              void* d_out, int out_size) {
    const float* x          = (const float*)d_in[0];
    const float* mask       = (const float*)d_in[1];
    const float* qkv_w      = (const float*)d_in[2];
    const float* qkv_b      = (const float*)d_in[3];
    const float* proj_w     = (const float*)d_in[4];
    const float* proj_b     = (const float*)d_in[5];
    const float* bias_table = (const float*)d_in[6];
    const int*   rel_index  = (const int*)d_in[7];
    float* out = (float*)d_out;

    const int nwin = in_sizes[0] / (NTOK * CDIM);

    cudaFuncSetAttribute(win_msa_kernel,
                         cudaFuncAttributeMaxDynamicSharedMemorySize,
                         SMEM_FLOATS * sizeof(float));

    win_msa_kernel<<<nwin, 256, SMEM_FLOATS * sizeof(float)>>>(
        x, mask, qkv_w, qkv_b, proj_w, proj_b, bias_table, rel_index, out);
}

// round 4
// speedup vs baseline: 1.0757x; 1.0757x over previous
#include <cuda_runtime.h>
#include <cstdint>

#define NTOK 49
#define CDIM 192
#define NH 6
#define HD 32
#define NWMASK 64
#define NREL 169
#define QSCALE 0.17677669529663687f  // 1/sqrt(32)

// SMEM layout (floats). Strides 196 (mod 32 = 4) keep row accesses spread.
#define XS_STRIDE 196
#define WS_STRIDE 196
#define XS_OFF 0
#define WS_OFF (64 * XS_STRIDE)                    // 12544
#define QS_OFF (WS_OFF + 64 * WS_STRIDE)           // 25088
#define KS_OFF (QS_OFF + NH * NTOK * HD)           // +9408
#define VS_OFF (KS_OFF + NH * NTOK * HD)
#define BT_OFF (VS_OFF + NH * NTOK * HD)
#define RI_OFF (BT_OFF + NREL * NH)                // +1014
#define SMEM_FLOATS (RI_OFF + NTOK * NTOK)         // 56727 -> 226908 B (< 232448)

typedef unsigned long long ull;

__device__ __forceinline__ void unpack2(ull v, float& lo, float& hi) {
    asm("mov.b64 {%0, %1}, %2;" : "=f"(lo), "=f"(hi) : "l"(v));
}
__device__ __forceinline__ ull pack2(float lo, float hi) {
    ull r;
    asm("mov.b64 %0, {%1, %2};" : "=l"(r) : "f"(lo), "f"(hi));
    return r;
}
// packed fp32 FMA (Blackwell): d = a*b + d elementwise on 2 lanes
__device__ __forceinline__ void fma2(ull& d, ull a, ull b) {
#if defined(__CUDA_ARCH__) && (__CUDA_ARCH__ >= 1000)
    asm("fma.rn.f32x2 %0, %1, %2, %3;" : "=l"(d) : "l"(a), "l"(b), "l"(d));
#else
    float dl, dh, al, ah, bl, bh;
    unpack2(d, dl, dh); unpack2(a, al, ah); unpack2(b, bl, bh);
    dl = fmaf(al, bl, dl); dh = fmaf(ah, bh, dh);
    d = pack2(dl, dh);
#endif
}

__device__ __forceinline__ void cp16(float* sm, const float* gm) {
    unsigned sa = (unsigned)__cvta_generic_to_shared(sm);
    asm volatile("cp.async.ca.shared.global [%0], [%1], 16;" :: "r"(sa), "l"(gm));
}

// 64x64 GEMM tile over K=192. Thread (tx 0-7, ty 0-31): rows {ty, ty+32},
// cols {tx + 8j, j=0..7}. f32x2 lanes = (even k, odd k) partial sums, so both
// operands load directly as 64-bit pairs — no packing MOVs. Horizontal add at
// the end. Rows 49-63 of xs are zeros.
__device__ __forceinline__ void gemm64(const float* __restrict__ smf,
                                       int tx, int ty, ull acc[2][8]) {
    const float* xs = smf + XS_OFF;
    const float* ws = smf + WS_OFF;
#pragma unroll
    for (int i = 0; i < 2; i++)
#pragma unroll
        for (int j = 0; j < 8; j++) acc[i][j] = 0ull;
    const ulonglong2* a0p = (const ulonglong2*)(xs + ty * XS_STRIDE);
    const ulonglong2* a1p = (const ulonglong2*)(xs + (ty + 32) * XS_STRIDE);
#pragma unroll 2
    for (int k4 = 0; k4 < 48; ++k4) {
        ulonglong2 a0 = a0p[k4];
        ulonglong2 a1 = a1p[k4];
#pragma unroll
        for (int j = 0; j < 8; ++j) {
            ulonglong2 b = *(const ulonglong2*)(ws + (tx + 8 * j) * WS_STRIDE + k4 * 4);
            fma2(acc[0][j], a0.x, b.x);
            fma2(acc[0][j], a0.y, b.y);
            fma2(acc[1][j], a1.x, b.x);
            fma2(acc[1][j], a1.y, b.y);
        }
    }
}

__global__ __launch_bounds__(256, 1)
void win_msa_kernel(const float* __restrict__ x, const float* __restrict__ mask,
                    const float* __restrict__ qkv_w, const float* __restrict__ qkv_b,
                    const float* __restrict__ proj_w, const float* __restrict__ proj_b,
                    const float* __restrict__ bias_table,
                    const int* __restrict__ rel_index,
                    float* __restrict__ out)
{
    extern __shared__ float smf[];
    float* xs = smf + XS_OFF;   // x tile (64 rows, 49 real), later attention output
    float* ws = smf + WS_OFF;   // weight tile 64 cols x 192 k, row-major like global
    float* qs = smf + QS_OFF;   // [h][n][32]
    float* ks = smf + KS_OFF;
    float* vs = smf + VS_OFF;
    float* bts = smf + BT_OFF;  // [169][6]
    int*   ris = (int*)(smf + RI_OFF);

    const int bw = blockIdx.x;
    const int tid = threadIdx.x;
    const int tx = tid & 7;
    const int ty = tid >> 3;

    // ---- stage x (49 rows), zero rows 49-63, stage bias_table + rel_index;
    //      async-prefetch qkv weight tile 0 ----
    {
        for (int it = tid; it < 64 * 48; it += 256) {
            int c = it / 48, k4 = it - c * 48;
            cp16(ws + c * WS_STRIDE + k4 * 4, qkv_w + c * CDIM + k4 * 4);
        }
        asm volatile("cp.async.commit_group;");

        const float4* gx = (const float4*)(x + (size_t)bw * NTOK * CDIM);
        for (int it = tid; it < NTOK * 48; it += 256) {
            int r = it / 48, k4 = it - r * 48;
            ((float4*)(xs + r * XS_STRIDE))[k4] = gx[it];
        }
        for (int it = tid; it < 15 * 48; it += 256) {
            int r = 49 + it / 48, k4 = it - (it / 48) * 48;
            ((float4*)(xs + r * XS_STRIDE))[k4] = make_float4(0.f, 0.f, 0.f, 0.f);
        }
        for (int it = tid; it < NREL * NH; it += 256) bts[it] = bias_table[it];
        for (int it = tid; it < NTOK * NTOK; it += 256) ris[it] = rel_index[it];
    }

    // ---- Phase 1: QKV projection, 9 column tiles of 64 ----
    for (int ct = 0; ct < 9; ++ct) {
        asm volatile("cp.async.wait_group 0;");
        __syncthreads();

        ull acc[2][8];
        gemm64(smf, tx, ty, acc);
        __syncthreads();  // ws reads complete before restage

        // prefetch next tile (or proj tile 0 across phase 2)
        const float* nw = (ct < 8) ? (qkv_w + (size_t)(ct + 1) * 64 * CDIM) : proj_w;
        for (int it = tid; it < 64 * 48; it += 256) {
            int c = it / 48, k4 = it - c * 48;
            cp16(ws + c * WS_STRIDE + k4 * 4, nw + c * CDIM + k4 * 4);
        }
        asm volatile("cp.async.commit_group;");

        const int s = ct / 3;  // 0=q,1=k,2=v
        float* dst = (s == 0) ? qs : (s == 1) ? ks : vs;
#pragma unroll
        for (int i = 0; i < 2; i++) {
            int r = ty + 32 * i;
            if (r < NTOK) {
#pragma unroll
                for (int j = 0; j < 8; j++) {
                    int cg = ct * 64 + tx + 8 * j;
                    float lo, hi; unpack2(acc[i][j], lo, hi);
                    float val = lo + hi + qkv_b[cg];
                    int rem = cg - s * CDIM;
                    int h = rem >> 5, d = rem & 31;
                    if (s == 0) val *= QSCALE;
                    dst[(h * NTOK + r) * HD + d] = val;
                }
            }
        }
    }
    __syncthreads();  // q/k/v visible

    // ---- Phase 2: attention, one (head, query-row) per thread ----
    for (int t = tid; t < NH * NTOK; t += 256) {
        const int h = t / NTOK;
        const int qi = t - h * NTOK;

        // q row as 16 packed pairs (adjacent d)
        ull qp[16];
        const ulonglong2* qrow = (const ulonglong2*)(qs + (h * NTOK + qi) * HD);
#pragma unroll
        for (int m = 0; m < 8; ++m) {
            ulonglong2 v2 = qrow[m];
            qp[2 * m] = v2.x; qp[2 * m + 1] = v2.y;
        }

        const float* mrow = mask + ((size_t)(bw & (NWMASK - 1)) * NTOK + qi) * NTOK;
        const int* ridx = ris + qi * NTOK;

        float p[NTOK];
        float mx = -1e30f;
        const float* kbase = ks + h * NTOK * HD;
#pragma unroll 1
        for (int j = 0; j < NTOK; ++j) {
            const ulonglong2* krow = (const ulonglong2*)(kbase + j * HD);
            ull a0 = 0ull, a1 = 0ull, a2 = 0ull, a3 = 0ull;
#pragma unroll
            for (int m = 0; m < 4; ++m) {
                ulonglong2 k0 = krow[2 * m];
                ulonglong2 k1 = krow[2 * m + 1];
                fma2(a0, qp[4 * m + 0], k0.x);
                fma2(a1, qp[4 * m + 1], k0.y);
                fma2(a2, qp[4 * m + 2], k1.x);
                fma2(a3, qp[4 * m + 3], k1.y);
            }
            float s0, s1, s2, s3, s4, s5, s6, s7;
            unpack2(a0, s0, s1); unpack2(a1, s2, s3);
            unpack2(a2, s4, s5); unpack2(a3, s6, s7);
            float s = ((s0 + s1) + (s2 + s3)) + ((s4 + s5) + (s6 + s7));
            s += bts[ridx[j] * NH + h] + mrow[j];
            p[j] = s;
            mx = fmaxf(mx, s);
        }

        // merged exp + PV accumulation (normalize at the end)
        ull o[16];
#pragma unroll
        for (int m = 0; m < 16; ++m) o[m] = 0ull;
        float sum = 0.f;
        const float* vbase = vs + h * NTOK * HD;
#pragma unroll 1
        for (int j = 0; j < NTOK; ++j) {
            float e = __expf(p[j] - mx);
            sum += e;
            ull pj = pack2(e, e);
            const ulonglong2* vrow = (const ulonglong2*)(vbase + j * HD);
#pragma unroll
            for (int m = 0; m < 8; ++m) {
                ulonglong2 vv = vrow[m];
                fma2(o[2 * m], pj, vv.x);
                fma2(o[2 * m + 1], pj, vv.y);
            }
        }
        const float rinv = 1.0f / sum;
        float* orow = xs + qi * XS_STRIDE + h * HD;
#pragma unroll
        for (int m = 0; m < 16; ++m) {
            float lo, hi; unpack2(o[m], lo, hi);
            orow[2 * m]     = lo * rinv;
            orow[2 * m + 1] = hi * rinv;
        }
    }
    __syncthreads();  // attention output in xs visible (rows 49-63 still zero)

    // ---- Phase 3: output projection, 3 column tiles of 64 ----
    for (int ct = 0; ct < 3; ++ct) {
        asm volatile("cp.async.wait_group 0;");
        __syncthreads();

        ull acc[2][8];
        gemm64(smf, tx, ty, acc);
        __syncthreads();

        if (ct < 2) {
            const float* nw = proj_w + (size_t)(ct + 1) * 64 * CDIM;
            for (int it = tid; it < 64 * 48; it += 256) {
                int c = it / 48, k4 = it - c * 48;
                cp16(ws + c * WS_STRIDE + k4 * 4, nw + c * CDIM + k4 * 4);
            }
            asm volatile("cp.async.commit_group;");
        }

#pragma unroll
        for (int i = 0; i < 2; i++) {
            int r = ty + 32 * i;
            if (r < NTOK) {
#pragma unroll
                for (int j = 0; j < 8; j++) {
                    int cg = ct * 64 + tx + 8 * j;
                    float lo, hi; unpack2(acc[i][j], lo, hi);
                    out[((size_t)bw * NTOK + r) * CDIM + cg] = lo + hi + proj_b[cg];
                }
            }
        }
    }
}

extern "C" void kernel_launch(void* const* d_in, const int* in_sizes, int n_in,
                              void* d_out, int out_size) {
    const float* x          = (const float*)d_in[0];
    const float* mask       = (const float*)d_in[1];
    const float* qkv_w      = (const float*)d_in[2];
    const float* qkv_b      = (const float*)d_in[3];
    const float* proj_w     = (const float*)d_in[4];
    const float* proj_b     = (const float*)d_in[5];
    const float* bias_table = (const float*)d_in[6];
    const int*   rel_index  = (const int*)d_in[7];
    float* out = (float*)d_out;

    const int nwin = in_sizes[0] / (NTOK * CDIM);

    cudaFuncSetAttribute(win_msa_kernel,
                         cudaFuncAttributeMaxDynamicSharedMemorySize,
                         SMEM_FLOATS * sizeof(float));

    win_msa_kernel<<<nwin, 256, SMEM_FLOATS * sizeof(float)>>>(
        x, mask, qkv_w, qkv_b, proj_w, proj_b, bias_table, rel_index, out);
}

// round 9
// speedup vs baseline: 2.1092x; 1.9608x over previous
#include <cuda_runtime.h>
#include <cstdint>

typedef unsigned int u32;
typedef unsigned long long ull;

#define NTOK 49
#define CDIM 192
#define NH 6
#define HD 32
#define NWMASK 64
#define NREL 169
#define QSCALE 0.17677669529663687f

// ---- smem layout (byte offsets) ----
#define ROWB 400                       // 200 halves/row: 25x16B, odd -> conflict-free ldmatrix
#define XH_B 0                         // x / attn-out, fp16 [64][200]     25600 B
#define WH0_B 25600                    // weight tile buf0 fp16 [64][200]  25600 B
#define WH1_B 51200                    // weight tile buf1                 25600 B
#define QS_B 76800                     // q fp32 [6][49][32]               37632 B
#define KS_B (QS_B + 37632)
#define VS_B (KS_B + 37632)
#define BTS_B (VS_B + 37632)           // bias_table fp32 [169][6]          4056 B
#define RIS_B (BTS_B + 4056)           // rel_index int [49*49]             9604 B
#define BIAS_B (RIS_B + 9604)          // qkv_b[576] then proj_b[192]       3072 B
#define SMEM_BYTES (BIAS_B + 3072)     // 206428 B (< 232448 opt-in)

__device__ __forceinline__ u32 smem_u32(const void* p) {
    u32 a;
    asm("{ .reg .u64 t; cvta.to.shared.u64 t, %1; cvt.u32.u64 %0, t; }" : "=r"(a) : "l"(p));
    return a;
}
// pack two fp32 -> fp16x2 (low half = lo)
__device__ __forceinline__ u32 f2h2(float lo, float hi) {
    u32 r;
    asm("cvt.rn.f16x2.f32 %0, %1, %2;" : "=r"(r) : "f"(hi), "f"(lo));
    return r;
}
__device__ __forceinline__ void unpack2(ull v, float& lo, float& hi) {
    asm("mov.b64 {%0, %1}, %2;" : "=f"(lo), "=f"(hi) : "l"(v));
}
__device__ __forceinline__ ull pack2(float lo, float hi) {
    ull r; asm("mov.b64 %0, {%1, %2};" : "=l"(r) : "f"(lo), "f"(hi)); return r;
}
__device__ __forceinline__ void fma2(ull& d, ull a, ull b) {
    asm("fma.rn.f32x2 %0, %1, %2, %3;" : "=l"(d) : "l"(a), "l"(b), "l"(d));
}

#define LDSM4(r0, r1, r2, r3, addr) \
    asm volatile("ldmatrix.sync.aligned.m8n8.x4.shared.b16 {%0,%1,%2,%3}, [%4];" \
        : "=r"(r0), "=r"(r1), "=r"(r2), "=r"(r3) : "r"(addr))

#define MMA16816(c, a0, a1, a2, a3, b0, b1) \
    asm volatile("mma.sync.aligned.m16n8k16.row.col.f32.f16.f16.f32 " \
        "{%0,%1,%2,%3}, {%4,%5,%6,%7}, {%8,%9}, {%0,%1,%2,%3};" \
        : "+f"((c)[0]), "+f"((c)[1]), "+f"((c)[2]), "+f"((c)[3]) \
        : "r"(a0), "r"(a1), "r"(a2), "r"(a3), "r"(b0), "r"(b1))

// convert one 64x192 fp32 weight tile -> fp16 [64][200] smem buffer
__device__ __forceinline__ void convert_W(char* sm, int buf_b,
                                          const float* __restrict__ w, int tid) {
    char* dst = sm + buf_b;
    for (int it = tid; it < 64 * 24; it += 256) {   // 24 8-half chunks per row
        int r = it / 24, k8 = it - r * 24;
        const float4* g = (const float4*)(w + r * CDIM + k8 * 8);
        float4 f0 = g[0], f1 = g[1];
        uint4 o;
        o.x = f2h2(f0.x, f0.y); o.y = f2h2(f0.z, f0.w);
        o.z = f2h2(f1.x, f1.y); o.w = f2h2(f1.z, f1.w);
        *(uint4*)(dst + r * ROWB + k8 * 16) = o;
    }
}

__global__ __launch_bounds__(256, 1)
void win_msa_kernel(const float* __restrict__ x, const float* __restrict__ mask,
                    const float* __restrict__ qkv_w, const float* __restrict__ qkv_b,
                    const float* __restrict__ proj_w, const float* __restrict__ proj_b,
                    const float* __restrict__ bias_table,
                    const int* __restrict__ rel_index,
                    float* __restrict__ out)
{
    extern __shared__ char sm[];
    float* qs = (float*)(sm + QS_B);
    float* ks = (float*)(sm + KS_B);
    float* vs = (float*)(sm + VS_B);
    float* bts = (float*)(sm + BTS_B);
    int*   ris = (int*)(sm + RIS_B);
    float* bias_sm = (float*)(sm + BIAS_B);

    const int bw = blockIdx.x;
    const int tid = threadIdx.x;
    const int lane = tid & 31;
    const int wrp = tid >> 5;
    const u32 smem_base = smem_u32(sm);

    // ---- staging: x -> fp16 xh, weight tile 0 -> buf0, tables ----
    {
        const float* gx = x + (size_t)bw * NTOK * CDIM;
        for (int it = tid; it < NTOK * 24; it += 256) {
            int r = it / 24, k8 = it - r * 24;
            const float4* g = (const float4*)(gx + r * CDIM + k8 * 8);
            float4 f0 = g[0], f1 = g[1];
            uint4 o;
            o.x = f2h2(f0.x, f0.y); o.y = f2h2(f0.z, f0.w);
            o.z = f2h2(f1.x, f1.y); o.w = f2h2(f1.z, f1.w);
            *(uint4*)(sm + XH_B + r * ROWB + k8 * 16) = o;
        }
        // zero pad rows 49-63
        for (int it = tid; it < 15 * 25; it += 256) {
            int r = 49 + it / 25, c16 = it % 25;
            *(uint4*)(sm + XH_B + r * ROWB + c16 * 16) = make_uint4(0, 0, 0, 0);
        }
        convert_W(sm, WH0_B, qkv_w, tid);
        for (int it = tid; it < 576; it += 256) bias_sm[it] = qkv_b[it];
        for (int it = tid; it < 192; it += 256) bias_sm[576 + it] = proj_b[it];
        for (int it = tid; it < NREL * NH; it += 256) bts[it] = bias_table[it];
        for (int it = tid; it < NTOK * NTOK; it += 256) ris[it] = rel_index[it];
    }
    __syncthreads();

    // per-warp tile coords: m-block (16 rows), n-half (32 cols)
    const int mb = wrp & 3;
    const int nh = wrp >> 2;
    const u32 lrow = (u32)((lane & 7) + ((lane >> 3) & 1) * 8);
    const u32 lk16 = (u32)(((lane >> 4) & 1) * 16);
    const u32 a_base = smem_base + XH_B + (mb * 16 + lrow) * ROWB + lk16;

    // ---- 12 GEMM tiles: 9 qkv + 3 proj ----
    for (int ct = 0; ct < 12; ++ct) {
        if (ct == 9) {
            // ======== attention (fp32), one (head, query-row) per thread ========
            for (int t = tid; t < NH * NTOK; t += 256) {
                const int h = t / NTOK;
                const int qi = t - h * NTOK;

                ull qp[16];
                const ulonglong2* qrow = (const ulonglong2*)(qs + (h * NTOK + qi) * HD);
#pragma unroll
                for (int m = 0; m < 8; ++m) {
                    ulonglong2 v2 = qrow[m];
                    qp[2 * m] = v2.x; qp[2 * m + 1] = v2.y;
                }
                const float* mrow = mask + ((size_t)(bw & (NWMASK - 1)) * NTOK + qi) * NTOK;
                const int* ridx = ris + qi * NTOK;

                float p[NTOK];
                float mx = -1e30f;
                const float* kbase = ks + h * NTOK * HD;
#pragma unroll 1
                for (int j = 0; j < NTOK; ++j) {
                    const ulonglong2* krow = (const ulonglong2*)(kbase + j * HD);
                    ull a0 = 0, a1 = 0, a2 = 0, a3 = 0;
#pragma unroll
                    for (int m = 0; m < 4; ++m) {
                        ulonglong2 k0 = krow[2 * m];
                        ulonglong2 k1 = krow[2 * m + 1];
                        fma2(a0, qp[4 * m + 0], k0.x);
                        fma2(a1, qp[4 * m + 1], k0.y);
                        fma2(a2, qp[4 * m + 2], k1.x);
                        fma2(a3, qp[4 * m + 3], k1.y);
                    }
                    float s0, s1, s2, s3, s4, s5, s6, s7;
                    unpack2(a0, s0, s1); unpack2(a1, s2, s3);
                    unpack2(a2, s4, s5); unpack2(a3, s6, s7);
                    float s = ((s0 + s1) + (s2 + s3)) + ((s4 + s5) + (s6 + s7));
                    s += bts[ridx[j] * NH + h] + mrow[j];
                    p[j] = s;
                    mx = fmaxf(mx, s);
                }
                ull o[16];
#pragma unroll
                for (int m = 0; m < 16; ++m) o[m] = 0;
                float sum = 0.f;
                const float* vbase = vs + h * NTOK * HD;
#pragma unroll 1
                for (int j = 0; j < NTOK; ++j) {
                    float e = __expf(p[j] - mx);
                    sum += e;
                    ull pj = pack2(e, e);
                    const ulonglong2* vrow = (const ulonglong2*)(vbase + j * HD);
#pragma unroll
                    for (int m = 0; m < 8; ++m) {
                        ulonglong2 vv = vrow[m];
                        fma2(o[2 * m], pj, vv.x);
                        fma2(o[2 * m + 1], pj, vv.y);
                    }
                }
                const float rinv = 1.0f / sum;
                // write o as fp16 into xh row qi, cols h*32..h*32+31
                char* orow = sm + XH_B + qi * ROWB + h * HD * 2;
#pragma unroll
                for (int m = 0; m < 16; ++m) {
                    float lo, hi; unpack2(o[m], lo, hi);
                    *(u32*)(orow + m * 4) = f2h2(lo * rinv, hi * rinv);
                }
            }
            __syncthreads();  // xh(attn out) visible to all warps for proj GEMM
        }

        // ---- GEMM 64x64x192 from weight buffer ct&1 ----
        const u32 wb = smem_base + (u32)((ct & 1) ? WH1_B : WH0_B);
        const u32 b0_base = wb + (nh * 32 + lrow) * ROWB + lk16;
        const u32 b1_base = b0_base + 16 * ROWB;

        float c[4][4];
#pragma unroll
        for (int i = 0; i < 4; ++i)
#pragma unroll
            for (int j = 0; j < 4; ++j) c[i][j] = 0.f;

        u32 aaddr = a_base, b0addr = b0_base, b1addr = b1_base;
#pragma unroll
        for (int kk = 0; kk < 12; ++kk) {
            u32 a0, a1, a2, a3, p0, p1, p2, p3, q0, q1, q2, q3;
            LDSM4(a0, a1, a2, a3, aaddr);
            LDSM4(p0, p1, p2, p3, b0addr);
            LDSM4(q0, q1, q2, q3, b1addr);
            MMA16816(c[0], a0, a1, a2, a3, p0, p2);
            MMA16816(c[1], a0, a1, a2, a3, p1, p3);
            MMA16816(c[2], a0, a1, a2, a3, q0, q2);
            MMA16816(c[3], a0, a1, a2, a3, q1, q3);
            aaddr += 32; b0addr += 32; b1addr += 32;
        }

        // ---- epilogue straight from fragments ----
        {
            const int r0 = mb * 16 + (lane >> 2);
            const int colb = nh * 32 + 2 * (lane & 3);
            if (ct < 9) {
                const int s = ct / 3;
                const float sc = (s == 0) ? QSCALE : 1.0f;
                float* dst = (float*)(sm + ((s == 0) ? QS_B : (s == 1) ? KS_B : VS_B));
#pragma unroll
                for (int i = 0; i < 4; ++i) {
                    const int cg = ct * 64 + colb + i * 8;
                    const int rem = cg - s * CDIM;
                    const int h = rem >> 5, d = rem & 31;
                    const float b0 = bias_sm[cg], b1 = bias_sm[cg + 1];
                    if (r0 < NTOK) {
                        float2 v = make_float2((c[i][0] + b0) * sc, (c[i][1] + b1) * sc);
                        *(float2*)(dst + (h * NTOK + r0) * HD + d) = v;
                    }
                    if (r0 + 8 < NTOK) {
                        float2 v = make_float2((c[i][2] + b0) * sc, (c[i][3] + b1) * sc);
                        *(float2*)(dst + (h * NTOK + r0 + 8) * HD + d) = v;
                    }
                }
            } else {
#pragma unroll
                for (int i = 0; i < 4; ++i) {
                    const int cg = (ct - 9) * 64 + colb + i * 8;
                    const float b0 = bias_sm[576 + cg], b1 = bias_sm[576 + cg + 1];
                    if (r0 < NTOK) {
                        float2 v = make_float2(c[i][0] + b0, c[i][1] + b1);
                        *(float2*)(out + ((size_t)bw * NTOK + r0) * CDIM + cg) = v;
                    }
                    if (r0 + 8 < NTOK) {
                        float2 v = make_float2(c[i][2] + b0, c[i][3] + b1);
                        *(float2*)(out + ((size_t)bw * NTOK + r0 + 8) * CDIM + cg) = v;
                    }
                }
            }
        }

        // convert next weight tile into the other buffer
        if (ct < 11) {
            const float* nw = (ct + 1 < 9) ? (qkv_w + (size_t)(ct + 1) * 64 * CDIM)
                                           : (proj_w + (size_t)(ct + 1 - 9) * 64 * CDIM);
            convert_W(sm, ((ct + 1) & 1) ? WH1_B : WH0_B, nw, tid);
        }
        __syncthreads();
    }
}

extern "C" void kernel_launch(void* const* d_in, const int* in_sizes, int n_in,
                              void* d_out, int out_size) {
    const float* x          = (const float*)d_in[0];
    const float* mask       = (const float*)d_in[1];
    const float* qkv_w      = (const float*)d_in[2];
    const float* qkv_b      = (const float*)d_in[3];
    const float* proj_w     = (const float*)d_in[4];
    const float* proj_b     = (const float*)d_in[5];
    const float* bias_table = (const float*)d_in[6];
    const int*   rel_index  = (const int*)d_in[7];
    float* out = (float*)d_out;

    const int nwin = in_sizes[0] / (NTOK * CDIM);

    cudaFuncSetAttribute(win_msa_kernel,
                         cudaFuncAttributeMaxDynamicSharedMemorySize, SMEM_BYTES);

    win_msa_kernel<<<nwin, 256, SMEM_BYTES>>>(
        x, mask, qkv_w, qkv_b, proj_w, proj_b, bias_table, rel_index, out);
}

// round 10
// speedup vs baseline: 2.3937x; 1.1348x over previous
#include <cuda_runtime.h>
#include <cstdint>

typedef unsigned int u32;
typedef unsigned long long ull;

#define NTOK 49
#define CDIM 192
#define NH 6
#define HD 32
#define KVS 36                         // q/k/v row stride in floats (144 B, 16B-aligned)
#define NWMASK 64
#define NREL 169
#define QSCALE 0.17677669529663687f

// ---- smem layout (byte offsets) ----
#define ROWB 400                       // 200 halves/row: 25x16B, odd -> conflict-free ldmatrix
#define XH_B 0                         // x / attn-out fp16 [64][200]      25600 B
#define WH0_B 25600                    // weight tile buf0 fp16            25600 B
#define WH1_B 51200                    // weight tile buf1                 25600 B
#define QS_B 76800                     // q fp32 [6][49][36]               42336 B
#define KS_B (QS_B + 42336)            // 119136
#define VS_B (KS_B + 42336)            // 161472
#define BTS_B (VS_B + 42336)           // 203808: bias_table fp32 [169][6]  4056 B
#define RIS_B (BTS_B + 4056)           // 207864: rel_index int [2401]      9604 B
#define BIAS_B (RIS_B + 9604)          // 217468: qkv_b[576]+proj_b[192]    3072 B
#define MSK_B (BIAS_B + 3072)          // 220540: mask window [49][49]      9604 B
#define SMEM_BYTES (MSK_B + 9604)      // 230144 B (< 232448 opt-in)

__device__ __forceinline__ u32 smem_u32(const void* p) {
    u32 a;
    asm("{ .reg .u64 t; cvta.to.shared.u64 t, %1; cvt.u32.u64 %0, t; }" : "=r"(a) : "l"(p));
    return a;
}
__device__ __forceinline__ u32 f2h2(float lo, float hi) {
    u32 r;
    asm("cvt.rn.f16x2.f32 %0, %1, %2;" : "=r"(r) : "f"(hi), "f"(lo));
    return r;
}
__device__ __forceinline__ void unpack2(ull v, float& lo, float& hi) {
    asm("mov.b64 {%0, %1}, %2;" : "=f"(lo), "=f"(hi) : "l"(v));
}
__device__ __forceinline__ ull pack2(float lo, float hi) {
    ull r; asm("mov.b64 %0, {%1, %2};" : "=l"(r) : "f"(lo), "f"(hi)); return r;
}
__device__ __forceinline__ void fma2(ull& d, ull a, ull b) {
    asm("fma.rn.f32x2 %0, %1, %2, %3;" : "=l"(d) : "l"(a), "l"(b), "l"(d));
}

#define LDSM4(r0, r1, r2, r3, addr) \
    asm volatile("ldmatrix.sync.aligned.m8n8.x4.shared.b16 {%0,%1,%2,%3}, [%4];" \
        : "=r"(r0), "=r"(r1), "=r"(r2), "=r"(r3) : "r"(addr))

#define MMA16816(c, a0, a1, a2, a3, b0, b1) \
    asm volatile("mma.sync.aligned.m16n8k16.row.col.f32.f16.f16.f32 " \
        "{%0,%1,%2,%3}, {%4,%5,%6,%7}, {%8,%9}, {%0,%1,%2,%3};" \
        : "+f"((c)[0]), "+f"((c)[1]), "+f"((c)[2]), "+f"((c)[3]) \
        : "r"(a0), "r"(a1), "r"(a2), "r"(a3), "r"(b0), "r"(b1))

// convert one 64x192 fp32 weight tile -> fp16 [64][200] smem buffer
__device__ __forceinline__ void convert_W(char* sm, int buf_b,
                                          const float* __restrict__ w, int tid) {
    char* dst = sm + buf_b;
    for (int it = tid; it < 64 * 24; it += 256) {
        int r = it / 24, k8 = it - r * 24;
        const float4* g = (const float4*)(w + r * CDIM + k8 * 8);
        float4 f0 = g[0], f1 = g[1];
        uint4 o;
        o.x = f2h2(f0.x, f0.y); o.y = f2h2(f0.z, f0.w);
        o.z = f2h2(f1.x, f1.y); o.w = f2h2(f1.z, f1.w);
        *(uint4*)(dst + r * ROWB + k8 * 16) = o;
    }
}

__global__ __launch_bounds__(256, 1)
void win_msa_kernel(const float* __restrict__ x, const float* __restrict__ mask,
                    const float* __restrict__ qkv_w, const float* __restrict__ qkv_b,
                    const float* __restrict__ proj_w, const float* __restrict__ proj_b,
                    const float* __restrict__ bias_table,
                    const int* __restrict__ rel_index,
                    float* __restrict__ out)
{
    extern __shared__ char sm[];
    float* qs = (float*)(sm + QS_B);
    float* ks = (float*)(sm + KS_B);
    float* vs = (float*)(sm + VS_B);
    float* bts = (float*)(sm + BTS_B);
    int*   ris = (int*)(sm + RIS_B);
    float* bias_sm = (float*)(sm + BIAS_B);
    float* msk = (float*)(sm + MSK_B);

    const int bw = blockIdx.x;
    const int tid = threadIdx.x;
    const int lane = tid & 31;
    const int wrp = tid >> 5;
    const u32 smem_base = smem_u32(sm);

    // ---- staging: x -> fp16 xh, weight tile 0, tables, mask window ----
    {
        const float* gx = x + (size_t)bw * NTOK * CDIM;
        for (int it = tid; it < NTOK * 24; it += 256) {
            int r = it / 24, k8 = it - r * 24;
            const float4* g = (const float4*)(gx + r * CDIM + k8 * 8);
            float4 f0 = g[0], f1 = g[1];
            uint4 o;
            o.x = f2h2(f0.x, f0.y); o.y = f2h2(f0.z, f0.w);
            o.z = f2h2(f1.x, f1.y); o.w = f2h2(f1.z, f1.w);
            *(uint4*)(sm + XH_B + r * ROWB + k8 * 16) = o;
        }
        for (int it = tid; it < 15 * 25; it += 256) {   // zero pad rows 49-63
            int r = 49 + it / 25, c16 = it % 25;
            *(uint4*)(sm + XH_B + r * ROWB + c16 * 16) = make_uint4(0, 0, 0, 0);
        }
        convert_W(sm, WH0_B, qkv_w, tid);
        for (int it = tid; it < 576; it += 256) bias_sm[it] = qkv_b[it];
        for (int it = tid; it < 192; it += 256) bias_sm[576 + it] = proj_b[it];
        for (int it = tid; it < NREL * NH; it += 256) bts[it] = bias_table[it];
        for (int it = tid; it < NTOK * NTOK; it += 256) ris[it] = rel_index[it];
        const float* gm = mask + (size_t)(bw & (NWMASK - 1)) * NTOK * NTOK;
        for (int it = tid; it < NTOK * NTOK; it += 256) msk[it] = gm[it];
    }
    __syncthreads();

    // per-warp GEMM tile coords
    const int mb = wrp & 3;
    const int nh = wrp >> 2;
    const u32 lrow = (u32)((lane & 7) + ((lane >> 3) & 1) * 8);
    const u32 lk16 = (u32)(((lane >> 4) & 1) * 16);
    const u32 a_base = smem_base + XH_B + (mb * 16 + lrow) * ROWB + lk16;

    // ---- 12 GEMM tiles: 9 qkv + 3 proj ----
    for (int ct = 0; ct < 12; ++ct) {
        if (ct == 9) {
            // ==== attention: item = (head, row-half); lane = query row ====
            // K/V rows identical across lanes -> smem broadcast reads.
            for (int item = wrp; item < 2 * NH; item += 8) {
                const int h = item >> 1;
                const int qi = (item & 1) * 32 + lane;
                const bool act = qi < NTOK;
                const int qir = act ? qi : NTOK - 1;

                ull qp[16];
                const ulonglong2* qrow = (const ulonglong2*)(qs + (h * NTOK + qir) * KVS);
#pragma unroll
                for (int m = 0; m < 8; ++m) {
                    ulonglong2 v2 = qrow[m];
                    qp[2 * m] = v2.x; qp[2 * m + 1] = v2.y;
                }
                const float* msk_r = msk + qir * NTOK;
                const int* ridx = ris + qir * NTOK;
                const float* kbase = ks + h * NTOK * KVS;

                float p[NTOK];
                float mx = -1e30f;
#pragma unroll 2
                for (int j = 0; j < NTOK; ++j) {
                    const ulonglong2* krow = (const ulonglong2*)(kbase + j * KVS);
                    ull a0 = 0, a1 = 0, a2 = 0, a3 = 0;
#pragma unroll
                    for (int m = 0; m < 4; ++m) {
                        ulonglong2 k0 = krow[2 * m];
                        ulonglong2 k1 = krow[2 * m + 1];
                        fma2(a0, qp[4 * m + 0], k0.x);
                        fma2(a1, qp[4 * m + 1], k0.y);
                        fma2(a2, qp[4 * m + 2], k1.x);
                        fma2(a3, qp[4 * m + 3], k1.y);
                    }
                    float s0, s1, s2, s3, s4, s5, s6, s7;
                    unpack2(a0, s0, s1); unpack2(a1, s2, s3);
                    unpack2(a2, s4, s5); unpack2(a3, s6, s7);
                    float s = ((s0 + s1) + (s2 + s3)) + ((s4 + s5) + (s6 + s7));
                    s += bts[ridx[j] * NH + h] + msk_r[j];
                    p[j] = s;
                    mx = fmaxf(mx, s);
                }

                ull o[16];
#pragma unroll
                for (int m = 0; m < 16; ++m) o[m] = 0;
                float sum = 0.f;
                const float* vbase = vs + h * NTOK * KVS;
#pragma unroll 1
                for (int j = 0; j < NTOK; ++j) {
                    float e = __expf(p[j] - mx);
                    sum += e;
                    ull pj = pack2(e, e);
                    const ulonglong2* vrow = (const ulonglong2*)(vbase + j * KVS);
#pragma unroll
                    for (int m = 0; m < 8; ++m) {
                        ulonglong2 vv = vrow[m];
                        fma2(o[2 * m], pj, vv.x);
                        fma2(o[2 * m + 1], pj, vv.y);
                    }
                }
                if (act) {
                    const float rinv = 1.0f / sum;
                    char* orow = sm + XH_B + qi * ROWB + h * HD * 2;
#pragma unroll
                    for (int m = 0; m < 16; ++m) {
                        float lo, hi; unpack2(o[m], lo, hi);
                        *(u32*)(orow + m * 4) = f2h2(lo * rinv, hi * rinv);
                    }
                }
            }
            __syncthreads();  // attn out in xh visible for proj GEMM
        }

        // ---- GEMM 64x64x192 from weight buffer ct&1 ----
        const u32 wb = smem_base + (u32)((ct & 1) ? WH1_B : WH0_B);
        const u32 b0_base = wb + (nh * 32 + lrow) * ROWB + lk16;
        const u32 b1_base = b0_base + 16 * ROWB;

        float c[4][4];
#pragma unroll
        for (int i = 0; i < 4; ++i)
#pragma unroll
            for (int j = 0; j < 4; ++j) c[i][j] = 0.f;

        u32 aaddr = a_base, b0addr = b0_base, b1addr = b1_base;
#pragma unroll
        for (int kk = 0; kk < 12; ++kk) {
            u32 a0, a1, a2, a3, p0, p1, p2, p3, q0, q1, q2, q3;
            LDSM4(a0, a1, a2, a3, aaddr);
            LDSM4(p0, p1, p2, p3, b0addr);
            LDSM4(q0, q1, q2, q3, b1addr);
            MMA16816(c[0], a0, a1, a2, a3, p0, p2);
            MMA16816(c[1], a0, a1, a2, a3, p1, p3);
            MMA16816(c[2], a0, a1, a2, a3, q0, q2);
            MMA16816(c[3], a0, a1, a2, a3, q1, q3);
            aaddr += 32; b0addr += 32; b1addr += 32;
        }

        // ---- epilogue straight from fragments ----
        {
            const int r0 = mb * 16 + (lane >> 2);
            const int colb = nh * 32 + 2 * (lane & 3);
            if (ct < 9) {
                const int s = ct / 3;
                const float sc = (s == 0) ? QSCALE : 1.0f;
                float* dst = (float*)(sm + ((s == 0) ? QS_B : (s == 1) ? KS_B : VS_B));
#pragma unroll
                for (int i = 0; i < 4; ++i) {
                    const int cg = ct * 64 + colb + i * 8;
                    const int rem = cg - s * CDIM;
                    const int h = rem >> 5, d = rem & 31;
                    const float b0 = bias_sm[cg], b1 = bias_sm[cg + 1];
                    if (r0 < NTOK) {
                        float2 v = make_float2((c[i][0] + b0) * sc, (c[i][1] + b1) * sc);
                        *(float2*)(dst + (h * NTOK + r0) * KVS + d) = v;
                    }
                    if (r0 + 8 < NTOK) {
                        float2 v = make_float2((c[i][2] + b0) * sc, (c[i][3] + b1) * sc);
                        *(float2*)(dst + (h * NTOK + r0 + 8) * KVS + d) = v;
                    }
                }
            } else {
#pragma unroll
                for (int i = 0; i < 4; ++i) {
                    const int cg = (ct - 9) * 64 + colb + i * 8;
                    const float b0 = bias_sm[576 + cg], b1 = bias_sm[576 + cg + 1];
                    if (r0 < NTOK) {
                        float2 v = make_float2(c[i][0] + b0, c[i][1] + b1);
                        *(float2*)(out + ((size_t)bw * NTOK + r0) * CDIM + cg) = v;
                    }
                    if (r0 + 8 < NTOK) {
                        float2 v = make_float2(c[i][2] + b0, c[i][3] + b1);
                        *(float2*)(out + ((size_t)bw * NTOK + r0 + 8) * CDIM + cg) = v;
                    }
                }
            }
        }

        // convert next weight tile into the other buffer
        if (ct < 11) {
            const float* nw = (ct + 1 < 9) ? (qkv_w + (size_t)(ct + 1) * 64 * CDIM)
                                           : (proj_w + (size_t)(ct + 1 - 9) * 64 * CDIM);
            convert_W(sm, ((ct + 1) & 1) ? WH1_B : WH0_B, nw, tid);
        }
        __syncthreads();
    }
}

extern "C" void kernel_launch(void* const* d_in, const int* in_sizes, int n_in,
                              void* d_out, int out_size) {
    const float* x          = (const float*)d_in[0];
    const float* mask       = (const float*)d_in[1];
    const float* qkv_w      = (const float*)d_in[2];
    const float* qkv_b      = (const float*)d_in[3];
    const float* proj_w     = (const float*)d_in[4];
    const float* proj_b     = (const float*)d_in[5];
    const float* bias_table = (const float*)d_in[6];
    const int*   rel_index  = (const int*)d_in[7];
    float* out = (float*)d_out;

    const int nwin = in_sizes[0] / (NTOK * CDIM);

    cudaFuncSetAttribute(win_msa_kernel,
                         cudaFuncAttributeMaxDynamicSharedMemorySize, SMEM_BYTES);

    win_msa_kernel<<<nwin, 256, SMEM_BYTES>>>(
        x, mask, qkv_w, qkv_b, proj_w, proj_b, bias_table, rel_index, out);
}